// round 13
// baseline (speedup 1.0000x reference)
#include <cuda_runtime.h>
#include <math.h>

#define NC   21
#define HW   (512 * 512)          // 2^18
#define NB   8
#define NPIX (NB * HW)            // 2,097,152
#define TPB  256
#define PPT  2                    // pixels per thread (float2)
#define NBLK (NPIX / (TPB * PPT)) // 4096
#define G0SZ 11                   // first channel burst
#define G1SZ 10                   // second channel burst

// Allocation-free scratch; zero at module load, reset by the last block after
// consumption so every call / graph replay stays deterministic.
__device__ float        g_cls_sum[NC];
__device__ int          g_cls_cnt[NC];
__device__ unsigned int g_done;

__global__ __launch_bounds__(TPB, 3)
void cbfocal_fused_kernel(const float* __restrict__ pred,
                          const float* __restrict__ target,
                          float* __restrict__ out) {
    __shared__ float s_sum[NC];
    __shared__ int   s_cnt[NC];
    __shared__ bool  s_last;

    int t = threadIdx.x;
    if (t < NC) { s_sum[t] = 0.0f; s_cnt[t] = 0; }
    __syncthreads();

    // 2 consecutive pixels per thread; both share the same batch index.
    long base = ((long)blockIdx.x * TPB + t) * PPT;
    int  b    = (int)(base >> 18);
    int  hw   = (int)(base & (HW - 1));     // even -> 8B aligned

    const float2* pp = (const float2*)(pred   + (((long)b * NC) << 18) + hw);
    const float2* tp = (const float2*)(target + (((long)b * NC) << 18) + hw);
    const long CSTRIDE2 = HW / 2;           // float2 per channel

    // Online sum-of-exp (inputs ~N(0,1): fp32-safe without max subtraction).
    float2 s   = make_float2(0.f, 0.f);
    float2 vc  = make_float2(0.f, 0.f);
    int2   cls = make_int2(0, 0);

    // Two giant bursts: {11, 10} channels. All 22 (resp. 20) LDG.64 issued
    // before any consumption — max per-warp request train, occupancy traded
    // down to 3 CTAs/SM for the register budget (evidence: DRAM% rises with
    // burst size and falls with occupancy across R4/R5/R6/R12).
    {
        float2 pv[G0SZ], tv[G0SZ];
        #pragma unroll
        for (int j = 0; j < G0SZ; j++) pv[j] = __ldcs(pp + j * CSTRIDE2);
        #pragma unroll
        for (int j = 0; j < G0SZ; j++) tv[j] = __ldcs(tp + j * CSTRIDE2);

        #pragma unroll
        for (int j = 0; j < G0SZ; j++) {
            s.x += __expf(pv[j].x);
            s.y += __expf(pv[j].y);
            if (tv[j].x > 0.5f) { cls.x = j; vc.x = pv[j].x; }
            if (tv[j].y > 0.5f) { cls.y = j; vc.y = pv[j].y; }
        }
    }
    {
        float2 pv[G1SZ], tv[G1SZ];
        #pragma unroll
        for (int j = 0; j < G1SZ; j++) pv[j] = __ldcs(pp + (G0SZ + j) * CSTRIDE2);
        #pragma unroll
        for (int j = 0; j < G1SZ; j++) tv[j] = __ldcs(tp + (G0SZ + j) * CSTRIDE2);

        #pragma unroll
        for (int j = 0; j < G1SZ; j++) {
            int c = G0SZ + j;
            s.x += __expf(pv[j].x);
            s.y += __expf(pv[j].y);
            if (tv[j].x > 0.5f) { cls.x = c; vc.x = pv[j].x; }
            if (tv[j].y > 0.5f) { cls.y = c; vc.y = pv[j].y; }
        }
    }

    {
        float lp, p, om;
        lp = vc.x - __logf(s.x); p = __expf(lp); om = 1.f - p;
        atomicAdd(&s_sum[cls.x], om * om * lp); atomicAdd(&s_cnt[cls.x], 1);
        lp = vc.y - __logf(s.y); p = __expf(lp); om = 1.f - p;
        atomicAdd(&s_sum[cls.y], om * om * lp); atomicAdd(&s_cnt[cls.y], 1);
    }
    __syncthreads();

    if (t < NC) {
        atomicAdd(&g_cls_sum[t], s_sum[t]);
        atomicAdd(&g_cls_cnt[t], s_cnt[t]);
    }

    // Last-block epilogue: weighted reduction + reset.
    __threadfence();
    if (t == 0) {
        unsigned int prev = atomicAdd(&g_done, 1u);
        s_last = (prev == (unsigned int)(gridDim.x - 1));
    }
    __syncthreads();

    if (s_last && t < 32) {
        const double n    = (double)NPIX;
        const double beta = (n - 1.0) / n;

        double val = 0.0;
        if (t < NC) {
            double w = (1.0 - beta) / (1.0 - pow(beta, (double)g_cls_cnt[t]) + 1e-6);
            val = w * (double)g_cls_sum[t];
        }
        #pragma unroll
        for (int o = 16; o > 0; o >>= 1) {
            val += __shfl_down_sync(0xffffffffu, val, o);
        }
        if (t < NC) { g_cls_sum[t] = 0.0f; g_cls_cnt[t] = 0; }
        if (t == 0) {
            g_done = 0u;
            out[0] = (float)(-val / n);
        }
    }
}

extern "C" void kernel_launch(void* const* d_in, const int* in_sizes, int n_in,
                              void* d_out, int out_size) {
    const float* pred   = (const float*)d_in[0];
    const float* target = (const float*)d_in[1];
    cbfocal_fused_kernel<<<NBLK, TPB>>>(pred, target, (float*)d_out);
}

// round 14
// speedup vs baseline: 1.1063x; 1.1063x over previous
#include <cuda_runtime.h>
#include <math.h>

#define NC    21
#define HW    (512 * 512)          // 2^18
#define NB    8
#define NPIX  (NB * HW)            // 2,097,152
#define TPB   256
#define PPT   2                    // pixels per thread (float2)
#define TILE  (TPB * PPT)          // 512 pixels per tile
#define NTIL  (NPIX / TILE)        // 4096 tiles
#define GRIDP (148 * 4)            // 592 persistent CTAs (4/SM on 148 SMs)
#define GRP   7                    // channels per load burst (21 = 3*7)

// Allocation-free scratch; zero at module load, reset by the last block after
// consumption so every call / graph replay stays deterministic.
__device__ float        g_cls_sum[NC];
__device__ int          g_cls_cnt[NC];
__device__ unsigned int g_done;

__global__ __launch_bounds__(TPB, 4)
void cbfocal_fused_kernel(const float* __restrict__ pred,
                          const float* __restrict__ target,
                          float* __restrict__ out) {
    __shared__ float s_sum[NC];
    __shared__ int   s_cnt[NC];
    __shared__ bool  s_last;

    int t = threadIdx.x;
    if (t < NC) { s_sum[t] = 0.0f; s_cnt[t] = 0; }
    __syncthreads();

    // Persistent loop: this CTA handles tiles bid, bid+592, bid+1184, ...
    for (int tt = blockIdx.x; tt < NTIL; tt += GRIDP) {
        long base = (long)tt * TILE;
        int  b    = (int)(base >> 18);
        int  hw   = (int)(base & (HW - 1)) + PPT * t;   // even -> 8B aligned

        const float2* pp = (const float2*)(pred   + (((long)b * NC) << 18) + hw);
        const float2* tp = (const float2*)(target + (((long)b * NC) << 18) + hw);
        const long CSTRIDE2 = HW / 2;

        // Online sum-of-exp (inputs ~N(0,1): fp32-safe without max subtraction).
        float2 s   = make_float2(0.f, 0.f);
        float2 vc  = make_float2(0.f, 0.f);
        int2   cls = make_int2(0, 0);

        // 3 bursts of 7 channels: all 14 LDG.64 issued before consumption.
        #pragma unroll
        for (int g = 0; g < NC / GRP; g++) {
            float2 pv[GRP], tv[GRP];
            #pragma unroll
            for (int j = 0; j < GRP; j++)
                pv[j] = __ldcs(pp + (g * GRP + j) * CSTRIDE2);
            #pragma unroll
            for (int j = 0; j < GRP; j++)
                tv[j] = __ldcs(tp + (g * GRP + j) * CSTRIDE2);

            #pragma unroll
            for (int j = 0; j < GRP; j++) {
                int c = g * GRP + j;
                s.x += __expf(pv[j].x);
                s.y += __expf(pv[j].y);
                if (tv[j].x > 0.5f) { cls.x = c; vc.x = pv[j].x; }
                if (tv[j].y > 0.5f) { cls.y = c; vc.y = pv[j].y; }
            }
        }

        float lp, p, om;
        lp = vc.x - __logf(s.x); p = __expf(lp); om = 1.f - p;
        atomicAdd(&s_sum[cls.x], om * om * lp); atomicAdd(&s_cnt[cls.x], 1);
        lp = vc.y - __logf(s.y); p = __expf(lp); om = 1.f - p;
        atomicAdd(&s_sum[cls.y], om * om * lp); atomicAdd(&s_cnt[cls.y], 1);
    }
    __syncthreads();

    // One global flush per CTA (was: per tile).
    if (t < NC) {
        atomicAdd(&g_cls_sum[t], s_sum[t]);
        atomicAdd(&g_cls_cnt[t], s_cnt[t]);
    }

    // Last-CTA epilogue: weighted reduction + reset.
    __threadfence();
    if (t == 0) {
        unsigned int prev = atomicAdd(&g_done, 1u);
        s_last = (prev == (unsigned int)(gridDim.x - 1));
    }
    __syncthreads();

    if (s_last && t < 32) {
        const double n    = (double)NPIX;
        const double beta = (n - 1.0) / n;

        double val = 0.0;
        if (t < NC) {
            double w = (1.0 - beta) / (1.0 - pow(beta, (double)g_cls_cnt[t]) + 1e-6);
            val = w * (double)g_cls_sum[t];
        }
        #pragma unroll
        for (int o = 16; o > 0; o >>= 1) {
            val += __shfl_down_sync(0xffffffffu, val, o);
        }
        if (t < NC) { g_cls_sum[t] = 0.0f; g_cls_cnt[t] = 0; }
        if (t == 0) {
            g_done = 0u;
            out[0] = (float)(-val / n);
        }
    }
}

extern "C" void kernel_launch(void* const* d_in, const int* in_sizes, int n_in,
                              void* d_out, int out_size) {
    const float* pred   = (const float*)d_in[0];
    const float* target = (const float*)d_in[1];
    cbfocal_fused_kernel<<<GRIDP, TPB>>>(pred, target, (float*)d_out);
}

// round 15
// speedup vs baseline: 1.1146x; 1.0075x over previous
#include <cuda_runtime.h>
#include <math.h>

#define NC    21
#define HW    (512 * 512)          // 2^18
#define NB    8
#define NPIX  (NB * HW)            // 2,097,152
#define TPB   256
#define PPT   2                    // pixels per thread (float2)
#define TILE  (TPB * PPT)          // 512 pixels per tile
#define NTIL  (NPIX / TILE)        // 4096 tiles
#define GRIDP (148 * 4)            // 592 persistent CTAs (4/SM on 148 SMs)
#define GRP   7                    // channels per load burst (21 = 3*7)

// Allocation-free scratch; zero at module load, reset by the last block after
// consumption so every call / graph replay stays deterministic.
__device__ float        g_cls_sum[NC];
__device__ int          g_cls_cnt[NC];
__device__ unsigned int g_done;

__global__ __launch_bounds__(TPB, 4)
void cbfocal_fused_kernel(const float* __restrict__ pred,
                          const float* __restrict__ target,
                          float* __restrict__ out) {
    __shared__ float s_sum[NC];
    __shared__ int   s_cnt[NC];
    __shared__ bool  s_last;

    int t = threadIdx.x;
    if (t < NC) { s_sum[t] = 0.0f; s_cnt[t] = 0; }
    __syncthreads();

    const long CSTRIDE2 = HW / 2;

    // Persistent loop: this CTA handles tiles bid, bid+592, bid+1184, ...
    for (int tt = blockIdx.x; tt < NTIL; tt += GRIDP) {
        long base = (long)tt * TILE;
        int  b    = (int)(base >> 18);
        int  hw   = (int)(base & (HW - 1)) + PPT * t;   // even -> 8B aligned

        const float2* pp = (const float2*)(pred   + (((long)b * NC) << 18) + hw);
        const float2* tp = (const float2*)(target + (((long)b * NC) << 18) + hw);

        // Online sum-of-exp (inputs ~N(0,1): fp32-safe without max subtraction).
        float2 s   = make_float2(0.f, 0.f);
        float2 ec  = make_float2(1.f, 1.f);   // exp(v_class), reused for p
        float2 vc  = make_float2(0.f, 0.f);
        int2   cls = make_int2(0, 0);

        // 3 bursts of 7 channels. Loads interleaved pred/target so consecutive
        // LSU requests alternate between the two far-apart address regions
        // (more uniform L2-slice/die utilization than 7+7 same-tensor runs).
        #pragma unroll
        for (int g = 0; g < NC / GRP; g++) {
            float2 pv[GRP], tv[GRP];
            #pragma unroll
            for (int j = 0; j < GRP; j++) {
                pv[j] = __ldcs(pp + (g * GRP + j) * CSTRIDE2);
                tv[j] = __ldcs(tp + (g * GRP + j) * CSTRIDE2);
            }

            #pragma unroll
            for (int j = 0; j < GRP; j++) {
                int c = g * GRP + j;
                float ex = __expf(pv[j].x);
                float ey = __expf(pv[j].y);
                s.x += ex;
                s.y += ey;
                if (tv[j].x > 0.5f) { cls.x = c; vc.x = pv[j].x; ec.x = ex; }
                if (tv[j].y > 0.5f) { cls.y = c; vc.y = pv[j].y; ec.y = ey; }
            }
        }

        // p = exp(vc)/s reuses the exp from the sum; log only for lp.
        float lp, p, om;
        lp = vc.x - __logf(s.x); p = ec.x / s.x; om = 1.f - p;
        atomicAdd(&s_sum[cls.x], om * om * lp); atomicAdd(&s_cnt[cls.x], 1);
        lp = vc.y - __logf(s.y); p = ec.y / s.y; om = 1.f - p;
        atomicAdd(&s_sum[cls.y], om * om * lp); atomicAdd(&s_cnt[cls.y], 1);
    }
    __syncthreads();

    // One global flush per CTA.
    if (t < NC) {
        atomicAdd(&g_cls_sum[t], s_sum[t]);
        atomicAdd(&g_cls_cnt[t], s_cnt[t]);
    }

    // Last-CTA epilogue: weighted reduction + reset.
    __threadfence();
    if (t == 0) {
        unsigned int prev = atomicAdd(&g_done, 1u);
        s_last = (prev == (unsigned int)(gridDim.x - 1));
    }
    __syncthreads();

    if (s_last && t < 32) {
        const double n    = (double)NPIX;
        const double beta = (n - 1.0) / n;

        double val = 0.0;
        if (t < NC) {
            double w = (1.0 - beta) / (1.0 - pow(beta, (double)g_cls_cnt[t]) + 1e-6);
            val = w * (double)g_cls_sum[t];
        }
        #pragma unroll
        for (int o = 16; o > 0; o >>= 1) {
            val += __shfl_down_sync(0xffffffffu, val, o);
        }
        if (t < NC) { g_cls_sum[t] = 0.0f; g_cls_cnt[t] = 0; }
        if (t == 0) {
            g_done = 0u;
            out[0] = (float)(-val / n);
        }
    }
}

extern "C" void kernel_launch(void* const* d_in, const int* in_sizes, int n_in,
                              void* d_out, int out_size) {
    const float* pred   = (const float*)d_in[0];
    const float* target = (const float*)d_in[1];
    cbfocal_fused_kernel<<<GRIDP, TPB>>>(pred, target, (float*)d_out);
}